// round 16
// baseline (speedup 1.0000x reference)
#include <cuda_runtime.h>
#include <math.h>
#include <stdint.h>

#define NTOT   131072
#define CEMB   32
#define CPE    128
#define INDIM  202
#define NF4    512
#define NF2    256
#define NHEAD  129
#define NFEAT  128
#define FINEIN 330
#define KPF    336
#define KSEL   26214
#define MT     26368
#define NLOW   8192
#define INVF        0.9999950000374997f
#define TWO_PI_F    6.2831854820251465f
#define HALF_PI_F   1.5707963705062866f

// ---------------- scratch ----------------
__device__ float g_lowT   [ (size_t)160 * NLOW ];
__device__ float g_embw   [ (size_t)NLOW * NF4 ];
__device__ float g_posy   [ 256 * NF4 ];
__device__ float g_posx   [ 256 * NF4 ];
__device__ float g_x1T    [ (size_t)NF4 * NTOT ];
__device__ float g_x2T    [ (size_t)NF2 * NTOT ];
__device__ float g_head   [ (size_t)NTOT * NFEAT ];
__device__ float g_hcol   [ NTOT ];
__device__ float g_segc   [ NTOT ];
__device__ float g_var    [ NTOT ];
__device__ float g_fineinT[ (size_t)KPF * MT ];
__device__ float g_y1T    [ (size_t)NFEAT * MT ];
__device__ float g_y2T    [ (size_t)NFEAT * MT ];
__device__ float g_zT     [ (size_t)64 * MT ];
__device__ float g_w2p    [ 256 * 128 ];
__device__ float g_w2c    [ 256 ];
// pre-dupped B images: [bnBlock][chunk][4096] (exact smem layout)
__device__ float g_w0ad   [ 4 * 10 * 4096 ];
__device__ float g_w0bd   [ 2 * 32 * 4096 ];
__device__ float g_w2pd   [ 1 * 16 * 4096 ];
__device__ float g_w1ad   [ 1 * 21 * 4096 ];
__device__ float g_w1bd   [ 1 *  8 * 4096 ];
__device__ float g_w3ad   [ 1 *  8 * 4096 ];
__device__ int   g_sel    [ KSEL ];
__device__ int   g_eq     [ 8192 ];
__device__ unsigned g_hist[3][2048];
__device__ unsigned g_cnt_gt, g_cnt_eq;
__device__ unsigned g_thresh_bits;
__device__ int      g_need_eq;
__device__ unsigned g_bin[3];
__device__ unsigned g_need_s;
__device__ int      g_maskmode;
__device__ float g_tab[256][20];
__device__ float g_coord[256];

// ---------------- cp.async helpers ----------------
__device__ __forceinline__ void cpasync16(uint32_t saddr, const void* gaddr) {
    asm volatile("cp.async.cg.shared.global [%0], [%1], 16;" :: "r"(saddr), "l"(gaddr));
}
#define CP_COMMIT() asm volatile("cp.async.commit_group;" ::: "memory")
#define CP_WAIT0()  asm volatile("cp.async.wait_group 0;" ::: "memory")

// ---------------- mask dtype ----------------
__device__ __forceinline__ float maskval(const void* p, size_t idx, int mode) {
    switch (mode) {
        case 0: return ((const unsigned char*)p)[idx] ? 1.f : 0.f;
        case 1: return ((const int*)p)[idx] ? 1.f : 0.f;
        case 2: return ((const float*)p)[idx];
        case 3: return ((const long long*)p)[idx] ? 1.f : 0.f;
        default: return (float)((const double*)p)[idx];
    }
}

// ---------------- merged prelude ----------------
__global__ void k_prelude(const unsigned* __restrict__ dm, const float* __restrict__ w2) {
    int bid = blockIdx.x, t = threadIdx.x;
    if (bid == 0) {
        __shared__ int sf[4];
        if (t < 4) sf[t] = 0;
        __syncthreads();
        bool f32 = false, f64 = false, gt1 = false, oddnz = false;
        for (int i = t; i < 2048; i += 256) {
            unsigned v = dm[i];
            if (v == 0x3F800000u) f32 = true;
            else if (v == 0x3FF00000u) { if (i & 1) f64 = true; else gt1 = true; }
            else if (v > 1u) gt1 = true;
            if ((i & 1) && v) oddnz = true;
        }
        if (f32)  atomicOr(&sf[0], 1);
        if (f64)  atomicOr(&sf[1], 1);
        if (gt1)  atomicOr(&sf[2], 1);
        if (oddnz) atomicOr(&sf[3], 1);
        __syncthreads();
        if (t == 0) {
            int mode;
            if (sf[1]) mode = 4;
            else if (sf[0]) mode = 2;
            else if (sf[2]) mode = 0;
            else if (!sf[3]) mode = 3;
            else mode = 1;
            g_maskmode = mode;
        }
    } else if (bid == 1) {
        unsigned* h = &g_hist[0][0];
        for (int i = t; i < 3 * 2048; i += 256) h[i] = 0u;
        if (t == 0) { g_cnt_gt = 0u; g_cnt_eq = 0u; }
    } else if (bid == 2) {
        const float step = 2.0f / 255.0f;
        float c = __fadd_rn(-1.0f, __fmul_rn((float)t, step));
        g_coord[t] = c;
        float sc = __fmul_rn(TWO_PI_F, c);
        const float f109 = 10.0f / 9.0f;
        for (int j = 0; j < 10; j++) {
            float xj = __fmul_rn((float)j, f109);
            float fr = (float)exp2((double)xj);
            float ph = __fmul_rn(sc, fr);
            g_tab[t][j]      = (float)sin((double)ph);
            float ph2 = __fadd_rn(ph, HALF_PI_F);
            g_tab[t][10 + j] = (float)sin((double)ph2);
        }
    } else {
        int i = (bid - 3) * 256 + t;
        if (i < 256 * 129) {
            int k = i / 129, j = i - k * 129;
            float v = w2[i];
            if (j < 128) g_w2p[k * 128 + j] = v;
            else g_w2c[k] = v;
        }
    }
}

// ---------------- build pre-dupped B image (exact replay of LOADB/STOREB) -----
__global__ void k_dupB(const float* __restrict__ B, int ldB, int Klog, int N,
                       float* __restrict__ out, int nCh) {
    int bnb = blockIdx.x / nCh, ch = blockIdx.x - bnb * nCh;
    int t = threadIdx.x;
    float* reg = out + (size_t)blockIdx.x * 4096;
    const float4* B4 = (const float4*)B;
    int ldb4 = ldB >> 2;
    #pragma unroll
    for (int i = 0; i < 2; i++) {
        int f = t + 256 * i;
        int kk = f >> 5, c4 = f & 31;
        int gk = ch * 16 + kk, gn = bnb * 128 + c4 * 4;
        float4 v;
        if (gk < Klog && gn < N) v = B4[(size_t)gk * ldb4 + (gn >> 2)];
        else v = make_float4(0.f, 0.f, 0.f, 0.f);
        int tcb = c4 >> 1, qb = (c4 & 1) * 2;
        *(float4*)&reg[((kk * 4 + qb) * 16 + tcb) * 4] =
            make_float4(v.x, v.x, v.y, v.y);
        *(float4*)&reg[((kk * 4 + qb + 1) * 16 + tcb) * 4] =
            make_float4(v.z, v.z, v.w, v.w);
    }
}

// ---------------- low-res feat (transposed) ----------------
__global__ void k_lowT(const float* __restrict__ emb, const float* __restrict__ pe) {
    int idx = blockIdx.x * 256 + threadIdx.x;
    if (idx >= 160 * NLOW) return;
    int c = idx >> 13;
    int m = idx & (NLOW - 1);
    int b = m >> 12, p = m & 4095;
    float v = (c < CEMB) ? emb[((size_t)(b * CEMB + c)) * 4096 + p]
                         : pe [((size_t)(b * CPE + (c - CEMB))) * 4096 + p];
    g_lowT[idx] = v;
}

// ---------------- pos weight tables ----------------
__global__ void k_posw(const float* __restrict__ w0a) {
    int idx = blockIdx.x * 256 + threadIdx.x;
    if (idx >= 256 * NF4) return;
    int v = idx >> 9, j = idx & 511;
    float ay = 0.f, ax = 0.f;
    #pragma unroll
    for (int t = 0; t < 10; t++) ay = fmaf(g_tab[v][t],      w0a[(160 + t) * NF4 + j], ay);
    #pragma unroll
    for (int t = 0; t < 10; t++) ay = fmaf(g_tab[v][10 + t], w0a[(180 + t) * NF4 + j], ay);
    ay = fmaf(g_coord[v], w0a[200 * NF4 + j], ay);
    #pragma unroll
    for (int t = 0; t < 10; t++) ax = fmaf(g_tab[v][t],      w0a[(170 + t) * NF4 + j], ax);
    #pragma unroll
    for (int t = 0; t < 10; t++) ax = fmaf(g_tab[v][10 + t], w0a[(190 + t) * NF4 + j], ax);
    ax = fmaf(g_coord[v], w0a[201 * NF4 + j], ax);
    g_posy[idx] = ay;
    g_posx[idx] = ax;
}

// ---------------- FFMA2 SGEMM, full cp.async staging (A + pre-dupped B) -------
#define FFMA2(d,a,b) asm("fma.rn.f32x2 %0, %1, %2, %0;" : "+l"(d) : "l"(a), "l"(b))

template<int EPI, int TRANSC>
__global__ void __launch_bounds__(256, 1) k_gemmA(
    const float* __restrict__ At, const float* __restrict__ BdG,
    const float* __restrict__ bias, const float* __restrict__ g,
    const float* __restrict__ be, float* __restrict__ C,
    int M, int N, int ldA, int ldC, int nCh)
{
    extern __shared__ float sm[];
    float* As = sm;
    float* Bd = sm + 8192;
    const int t = threadIdx.x;
    const int bm = blockIdx.y * 256, bn = blockIdx.x * 128;
    const int bnb = blockIdx.x;
    const int tr = t >> 4, tc = t & 15;

    const float4* At4 = (const float4*)At;
    const int lda4 = ldA >> 2;
    const uint32_t sAs = (uint32_t)__cvta_generic_to_shared(As);
    const uint32_t sBd = (uint32_t)__cvta_generic_to_shared(Bd);

    unsigned long long acc[8][8];
    #pragma unroll
    for (int i = 0; i < 8; i++)
        #pragma unroll
        for (int j = 0; j < 8; j++) acc[i][j] = 0ull;

    auto LOADAB = [&](int it, int buf) {
        uint32_t abase = sAs + (unsigned)buf * 4096u * 4u;
        int k0 = it * 16;
        #pragma unroll
        for (int i = 0; i < 4; i++) {
            int f = t + 256 * i;
            int kk = f >> 6, m4 = f & 63;
            cpasync16(abase + (unsigned)(kk * 256 + m4 * 4) * 4u,
                      &At4[(size_t)(k0 + kk) * lda4 + (bm >> 2) + m4]);
        }
        uint32_t bbase = sBd + (unsigned)buf * 4096u * 4u;
        const float4* src = (const float4*)(BdG + (size_t)(bnb * nCh + it) * 4096);
        #pragma unroll
        for (int i = 0; i < 4; i++) {
            int f = t + 256 * i;
            cpasync16(bbase + (unsigned)f * 16u, &src[f]);
        }
    };
    auto COMPUTE = [&](int buf) {
        const float* Asb = As + buf * 4096;
        const float* Bdb = Bd + buf * 4096;
        #pragma unroll
        for (int kk = 0; kk < 16; kk++) {
            unsigned long long a2[8], b2[8];
            #pragma unroll
            for (int r = 0; r < 4; r++) {
                ulonglong2 v = *(const ulonglong2*)&Asb[kk * 256 + tr * 16 + r * 4];
                a2[2 * r] = v.x; a2[2 * r + 1] = v.y;
            }
            #pragma unroll
            for (int q = 0; q < 4; q++) {
                ulonglong2 v = *(const ulonglong2*)&Bdb[(kk * 4 + q) * 64 + tc * 4];
                b2[2 * q] = v.x; b2[2 * q + 1] = v.y;
            }
            #pragma unroll
            for (int ip = 0; ip < 8; ip++)
                #pragma unroll
                for (int j = 0; j < 8; j++)
                    FFMA2(acc[ip][j], a2[ip], b2[j]);
        }
    };

    LOADAB(0, 0);
    CP_COMMIT(); CP_WAIT0();
    __syncthreads();
    int buf = 0;
    for (int it = 1; it < nCh; it++) {
        LOADAB(it, buf ^ 1);
        CP_COMMIT();
        COMPUTE(buf);
        CP_WAIT0();
        __syncthreads();
        buf ^= 1;
    }
    COMPUTE(buf);

    if (TRANSC) {
        #pragma unroll
        for (int j = 0; j < 8; j++) {
            int gn = bn + tc * 8 + j;
            if (gn >= N) continue;
            float bsv = (EPI != 2) ? bias[gn] : 0.f;
            float sv = 0.f, bev = 0.f;
            if (EPI == 1) { sv = __fmul_rn(g[gn], INVF); bev = be[gn]; }
            float v[16];
            #pragma unroll
            for (int ip = 0; ip < 8; ip++) {
                v[2 * ip]     = __uint_as_float((unsigned)(acc[ip][j] & 0xFFFFFFFFull));
                v[2 * ip + 1] = __uint_as_float((unsigned)(acc[ip][j] >> 32));
            }
            #pragma unroll
            for (int r = 0; r < 16; r++) {
                float x = v[r];
                if (EPI != 2) x = __fadd_rn(x, bsv);
                if (EPI == 1) { x = __fadd_rn(__fmul_rn(x, sv), bev); x = fmaxf(x, 0.f); }
                v[r] = x;
            }
            int gmb = bm + tr * 16;
            if (gmb + 16 <= M) {
                #pragma unroll
                for (int r4 = 0; r4 < 4; r4++)
                    *(float4*)&C[(size_t)gn * ldC + gmb + r4 * 4] =
                        make_float4(v[r4 * 4], v[r4 * 4 + 1], v[r4 * 4 + 2], v[r4 * 4 + 3]);
            } else {
                for (int r = 0; r < 16; r++)
                    if (gmb + r < M) C[(size_t)gn * ldC + gmb + r] = v[r];
            }
        }
    } else {
        #pragma unroll
        for (int ip = 0; ip < 8; ip++) {
            #pragma unroll
            for (int h = 0; h < 2; h++) {
                int gm = bm + tr * 16 + 2 * ip + h;
                if (gm >= M) continue;
                float v[8];
                #pragma unroll
                for (int j = 0; j < 8; j++) {
                    unsigned long long a = acc[ip][j];
                    float x = h ? __uint_as_float((unsigned)(a >> 32))
                                : __uint_as_float((unsigned)(a & 0xFFFFFFFFull));
                    int gn = bn + tc * 8 + j;
                    if (EPI != 2) x = __fadd_rn(x, bias[gn]);
                    if (EPI == 1) {
                        x = __fadd_rn(__fmul_rn(x, __fmul_rn(g[gn], INVF)), be[gn]);
                        x = fmaxf(x, 0.f);
                    }
                    v[j] = x;
                }
                int gn0 = bn + tc * 8;
                if (gn0 + 8 <= N) {
                    *(float4*)&C[(size_t)gm * ldC + gn0]     = make_float4(v[0], v[1], v[2], v[3]);
                    *(float4*)&C[(size_t)gm * ldC + gn0 + 4] = make_float4(v[4], v[5], v[6], v[7]);
                } else {
                    for (int j = 0; j < 8; j++)
                        if (gn0 + j < N) C[(size_t)gm * ldC + gn0 + j] = v[j];
                }
            }
        }
    }
}

// ---------------- tiled upsample + pos + bn -> x1T (bit-exact) ----------------
#define UP_JT 32
__global__ void __launch_bounds__(256) k_up2(
    const float* __restrict__ b0a, const float* __restrict__ g0a,
    const float* __restrict__ be0a)
{
    extern __shared__ float su[];
    float* E  = su;
    float* PX = su + 12288;
    float* T  = su + 20480;
    float* PY = su + 22784;
    float* PR = su + 23296;
    const int t = threadIdx.x;
    const int j0 = blockIdx.x * UP_JT, y0 = blockIdx.y * 16, b = blockIdx.z;

    float cyf0 = ((float)y0 + 0.5f) * 0.25f - 0.5f;
    int base = max(0, (int)floorf(cyf0));

    for (int i = t; i < 6 * 64 * (UP_JT / 4); i += 256) {
        int r = i / (64 * (UP_JT / 4));
        int rem = i - r * 64 * (UP_JT / 4);
        int ix = rem / (UP_JT / 4), jq = rem % (UP_JT / 4);
        int gy = min(base + r, 63);
        *(float4*)&E[(r * 64 + ix) * UP_JT + jq * 4] =
            *(const float4*)&g_embw[((size_t)(b * 4096 + gy * 64 + ix)) * NF4 + j0 + jq * 4];
    }
    for (int i = t; i < 256 * (UP_JT / 4); i += 256) {
        int x = i / (UP_JT / 4), jq = i % (UP_JT / 4);
        *(float4*)&PX[x * UP_JT + jq * 4] = *(const float4*)&g_posx[x * NF4 + j0 + jq * 4];
    }
    if (t < 16 * (UP_JT / 4)) {
        int y = t / (UP_JT / 4), jq = t % (UP_JT / 4);
        *(float4*)&PY[y * UP_JT + jq * 4] = *(const float4*)&g_posy[(y0 + y) * NF4 + j0 + jq * 4];
    }
    if (t >= 128 && t < 128 + 3 * (UP_JT / 4)) {
        int a = (t - 128) / (UP_JT / 4), jq = (t - 128) % (UP_JT / 4);
        const float* src = (a == 0) ? b0a : (a == 1) ? g0a : be0a;
        *(float4*)&PR[a * UP_JT + jq * 4] = *(const float4*)&src[j0 + jq * 4];
    }
    __syncthreads();

    for (int yy = 0; yy < 16; yy++) {
        int y = y0 + yy;
        float cyf = ((float)y + 0.5f) * 0.25f - 0.5f;
        float fy0f = floorf(cyf);
        float fy = cyf - fy0f;
        int yi = (int)fy0f;
        int iy0 = min(max(yi, 0), 63), iy1 = min(max(yi + 1, 0), 63);
        bool yeq = (iy0 == iy1);
        float wy0 = 1.f - fy;
        int r0 = iy0 - base, r1 = iy1 - base;

        for (int i = t; i < 64 * (UP_JT / 4); i += 256) {
            int ix = i / (UP_JT / 4), jq = i % (UP_JT / 4);
            float4 v0 = *(const float4*)&E[(r0 * 64 + ix) * UP_JT + jq * 4];
            float4 vv;
            if (yeq) vv = v0;
            else {
                float4 v1 = *(const float4*)&E[(r1 * 64 + ix) * UP_JT + jq * 4];
                vv.x = __fadd_rn(__fmul_rn(v0.x, wy0), __fmul_rn(v1.x, fy));
                vv.y = __fadd_rn(__fmul_rn(v0.y, wy0), __fmul_rn(v1.y, fy));
                vv.z = __fadd_rn(__fmul_rn(v0.z, wy0), __fmul_rn(v1.z, fy));
                vv.w = __fadd_rn(__fmul_rn(v0.w, wy0), __fmul_rn(v1.w, fy));
            }
            *(float4*)&T[ix * 36 + jq * 4] = vv;
        }
        __syncthreads();

        int x = t;
        int k = x >> 2, xi = x & 3;
        int cL, cR; float fx; bool cp;
        if (xi < 2) { cL = max(k - 1, 0); cR = k; fx = (xi == 0) ? 0.625f : 0.875f; cp = (k == 0); }
        else        { cL = k; cR = min(k + 1, 63); fx = (xi == 2) ? 0.125f : 0.375f; cp = (k == 63); }
        float wx = 1.f - fx;
        size_t n = (size_t)b * 65536 + (size_t)y * 256 + x;

        #pragma unroll
        for (int jq = 0; jq < UP_JT / 4; jq++) {
            float4 TL = *(const float4*)&T[cL * 36 + jq * 4];
            float4 v;
            if (cp) v = TL;
            else {
                float4 TR = *(const float4*)&T[cR * 36 + jq * 4];
                v.x = __fadd_rn(__fmul_rn(TL.x, wx), __fmul_rn(TR.x, fx));
                v.y = __fadd_rn(__fmul_rn(TL.y, wx), __fmul_rn(TR.y, fx));
                v.z = __fadd_rn(__fmul_rn(TL.z, wx), __fmul_rn(TR.z, fx));
                v.w = __fadd_rn(__fmul_rn(TL.w, wx), __fmul_rn(TR.w, fx));
            }
            float4 py  = *(const float4*)&PY[yy * UP_JT + jq * 4];
            float4 px  = *(const float4*)&PX[x * UP_JT + jq * 4];
            float4 bsv = *(const float4*)&PR[0 * UP_JT + jq * 4];
            float4 gv  = *(const float4*)&PR[1 * UP_JT + jq * 4];
            float4 bev = *(const float4*)&PR[2 * UP_JT + jq * 4];
            v.x = __fadd_rn(__fadd_rn(__fadd_rn(v.x, py.x), px.x), bsv.x);
            v.y = __fadd_rn(__fadd_rn(__fadd_rn(v.y, py.y), px.y), bsv.y);
            v.z = __fadd_rn(__fadd_rn(__fadd_rn(v.z, py.z), px.z), bsv.z);
            v.w = __fadd_rn(__fadd_rn(__fadd_rn(v.w, py.w), px.w), bsv.w);
            v.x = fmaxf(__fadd_rn(__fmul_rn(v.x, __fmul_rn(gv.x, INVF)), bev.x), 0.f);
            v.y = fmaxf(__fadd_rn(__fmul_rn(v.y, __fmul_rn(gv.y, INVF)), bev.y), 0.f);
            v.z = fmaxf(__fadd_rn(__fmul_rn(v.z, __fmul_rn(gv.z, INVF)), bev.z), 0.f);
            v.w = fmaxf(__fadd_rn(__fmul_rn(v.w, __fmul_rn(gv.w, INVF)), bev.w), 0.f);
            int j = j0 + jq * 4;
            g_x1T[(size_t)(j + 0) * NTOT + n] = v.x;
            g_x1T[(size_t)(j + 1) * NTOT + n] = v.y;
            g_x1T[(size_t)(j + 2) * NTOT + n] = v.z;
            g_x1T[(size_t)(j + 3) * NTOT + n] = v.w;
        }
        __syncthreads();
    }
}

// ---------------- head col 128 ----------------
__global__ void k_hcol(const float* __restrict__ b2) {
    int n = blockIdx.x * 256 + threadIdx.x;
    float acc = 0.f;
    #pragma unroll 8
    for (int k = 0; k < 256; k++)
        acc = fmaf(g_x2T[(size_t)k * NTOT + n], g_w2c[k], acc);
    g_hcol[n] = __fadd_rn(acc, b2[128]);
}

// ---------------- head post: segc / var ----------------
__global__ void k_post(const void* __restrict__ dm1, const void* __restrict__ dm2) {
    int w = (int)((blockIdx.x * (size_t)blockDim.x + threadIdx.x) >> 5);
    int lane = threadIdx.x & 31;
    if (w >= NTOT) return;
    int mode = g_maskmode;
    float acc = 0.f;
    for (int c = lane; c < NHEAD; c += 32) {
        float h = (c < 128) ? g_head[(size_t)w * 128 + c] : g_hcol[w];
        size_t mi = (size_t)w * NHEAD + c;
        float m1 = maskval(dm1, mi, mode);
        float m2 = maskval(dm2, mi, mode);
        float o2 = __fmul_rn(__fmul_rn(h, m2), 2.0f);
        if (c == 0) g_segc[w] = o2;
        float o1 = __fmul_rn(__fmul_rn(h, m1), 2.0f);
        float d  = __fsub_rn(o1, o2);
        acc = __fadd_rn(acc, __fmul_rn(0.5f, __fmul_rn(d, d)));
    }
    #pragma unroll
    for (int o = 16; o; o >>= 1) acc = __fadd_rn(acc, __shfl_xor_sync(~0u, acc, o));
    if (!lane) g_var[w] = __fdiv_rn(acc, 129.0f);
}

// ---------------- top-k ----------------
__global__ void k_hist(int phase) {
    int i = blockIdx.x * blockDim.x + threadIdx.x;
    if (i >= NTOT) return;
    unsigned key = __float_as_uint(g_var[i]);
    if (phase == 0) atomicAdd(&g_hist[0][key >> 21], 1u);
    else if (phase == 1) {
        if ((key >> 21) == g_bin[0]) atomicAdd(&g_hist[1][(key >> 10) & 0x7FFu], 1u);
    } else {
        if ((key >> 10) == ((g_bin[0] << 11) | g_bin[1]))
            atomicAdd(&g_hist[2][key & 0x3FFu], 1u);
    }
}

__global__ void k_scan2(int phase) {
    __shared__ unsigned csum[256];
    __shared__ unsigned suf[256];
    int t = threadIdx.x;
    unsigned need = (phase == 0) ? (unsigned)KSEL : g_need_s;
    const unsigned* H = g_hist[phase];
    unsigned h[8]; unsigned s = 0;
    #pragma unroll
    for (int i = 0; i < 8; i++) { h[i] = H[t * 8 + i]; s += h[i]; }
    csum[t] = s;
    __syncthreads();
    if (t == 0) {
        unsigned a = 0;
        for (int u = 255; u >= 0; u--) { suf[u] = a; a += csum[u]; }
    }
    __syncthreads();
    unsigned se = suf[t];
    if (se < need && se + csum[t] >= need) {
        unsigned acc = se;
        int b = -1;
        int lo = (t == 0) ? 1 : 0;
        for (int i = 7; i >= lo; i--) {
            unsigned hh = h[i];
            if (acc + hh >= need) { b = t * 8 + i; break; }
            acc += hh;
        }
        if (b < 0) b = 0;
        g_bin[phase] = (unsigned)b;
        g_need_s = need - acc;
        if (phase == 2) {
            g_thresh_bits = (g_bin[0] << 21) | (g_bin[1] << 10) | (unsigned)b;
            g_need_eq = (int)(need - acc);
        }
    }
}

__global__ void k_compact(float* __restrict__ out) {
    int i = blockIdx.x * blockDim.x + threadIdx.x;
    if (i >= NTOT) return;
    float vv = g_segc[i];
    out[i] = vv;
    out[NTOT + i] = vv;
    unsigned key = __float_as_uint(g_var[i]);
    unsigned T = g_thresh_bits;
    if (key > T) {
        unsigned s = atomicAdd(&g_cnt_gt, 1u);
        g_sel[s] = i;
    } else if (key == T) {
        unsigned e = atomicAdd(&g_cnt_eq, 1u);
        if (e < 8192u) g_eq[e] = i;
    }
}

__global__ void k_eqsel() {
    int c = (int)g_cnt_eq; if (c > 8192) c = 8192;
    int need = g_need_eq;
    int G = KSEL - need;
    for (int i = threadIdx.x; i < c; i += blockDim.x) {
        int v = g_eq[i];
        int rank = 0;
        for (int j = 0; j < c; j++) rank += (g_eq[j] < v) ? 1 : 0;
        if (rank < need) g_sel[G + rank] = v;
    }
}

// ---------------- lazy fine-input build ----------------
__global__ void k_gatherfine(const float* __restrict__ emb, const float* __restrict__ pe,
                             const void* __restrict__ dm2) {
    size_t idx = (size_t)blockIdx.x * 256 + threadIdx.x;
    if (idx >= (size_t)KPF * MT) return;
    int c = (int)(idx / MT);
    int j = (int)(idx - (size_t)c * MT);
    float v = 0.f;
    if (j < KSEL && c < FINEIN) {
        int s = g_sel[j];
        int b = s >> 16, y = (s >> 8) & 255, x = s & 255;
        if (c < CEMB + CPE) {
            const float* plane = (c < CEMB)
                ? emb + ((size_t)(b * CEMB + c)) * 4096
                : pe  + ((size_t)(b * CPE + (c - CEMB))) * 4096;
            float cyf = ((float)y + 0.5f) * 0.25f - 0.5f;
            float cxf = ((float)x + 0.5f) * 0.25f - 0.5f;
            float fy0 = floorf(cyf), fx0 = floorf(cxf);
            float fy = cyf - fy0, fx = cxf - fx0;
            int y0 = (int)fy0, x0 = (int)fx0;
            int iy0 = min(max(y0, 0), 63), iy1 = min(max(y0 + 1, 0), 63);
            int ix0 = min(max(x0, 0), 63), ix1 = min(max(x0 + 1, 0), 63);
            float v00 = plane[iy0 * 64 + ix0], v01 = plane[iy0 * 64 + ix1];
            float v10 = plane[iy1 * 64 + ix0], v11 = plane[iy1 * 64 + ix1];
            float wy0 = 1.f - fy, wx0 = 1.f - fx;
            float t0, t1;
            if (iy0 == iy1) { t0 = v00; t1 = v01; }
            else {
                t0 = __fadd_rn(__fmul_rn(v00, wy0), __fmul_rn(v10, fy));
                t1 = __fadd_rn(__fmul_rn(v01, wy0), __fmul_rn(v11, fy));
            }
            v = (ix0 == ix1) ? t0
                : __fadd_rn(__fmul_rn(t0, wx0), __fmul_rn(t1, fx));
        } else if (c < INDIM) {
            int p = c - (CEMB + CPE);
            if      (p < 10) v = g_tab[y][p];
            else if (p < 20) v = g_tab[x][p - 10];
            else if (p < 30) v = g_tab[y][p - 10];
            else if (p < 40) v = g_tab[x][p - 20];
            else v = (p == 40) ? g_coord[y] : g_coord[x];
        } else {
            int col = c - 201;   // 1..128
            float h = (col < 128) ? g_head[(size_t)s * 128 + col] : g_hcol[s];
            float m2 = maskval(dm2, (size_t)s * NHEAD + col, g_maskmode);
            v = __fmul_rn(__fmul_rn(h, m2), 2.0f);
        }
    }
    g_fineinT[idx] = v;
}

// ---------------- final fine dot + scatter ----------------
__global__ void k_zdot(const float* __restrict__ w3b, const float* __restrict__ b3b,
                       float* __restrict__ out) {
    int j = (int)((blockIdx.x * (size_t)blockDim.x + threadIdx.x) >> 5);
    int lane = threadIdx.x & 31;
    if (j >= KSEL) return;
    float v0  = g_zT[(size_t)lane * MT + j];
    float v32 = g_zT[(size_t)(32 + lane) * MT + j];
    float acc = __fadd_rn(__fmul_rn(v0, w3b[lane]), __fmul_rn(v32, w3b[32 + lane]));
    #pragma unroll
    for (int o = 16; o; o >>= 1) acc = __fadd_rn(acc, __shfl_xor_sync(~0u, acc, o));
    if (!lane) out[NTOT + g_sel[j]] = __fadd_rn(acc, b3b[0]);
}

// ---------------- launch ----------------
extern "C" void kernel_launch(void* const* d_in, const int* in_sizes, int n_in,
                              void* d_out, int out_size) {
    const float* emb = (const float*)d_in[0];
    const float* pe  = (const float*)d_in[1];
    const void*  dm1 = d_in[2];
    const void*  dm2 = d_in[3];
    const float* w0a = (const float*)d_in[4];
    const float* b0a = (const float*)d_in[5];
    const float* g0a = (const float*)d_in[6];
    const float* be0a= (const float*)d_in[7];
    const float* w0b = (const float*)d_in[8];
    const float* b0b = (const float*)d_in[9];
    const float* g0b = (const float*)d_in[10];
    const float* be0b= (const float*)d_in[11];
    const float* w2  = (const float*)d_in[12];
    const float* b2  = (const float*)d_in[13];
    const float* w1a = (const float*)d_in[14];
    const float* b1a = (const float*)d_in[15];
    const float* g1a = (const float*)d_in[16];
    const float* be1a= (const float*)d_in[17];
    const float* w1b = (const float*)d_in[18];
    const float* b1b = (const float*)d_in[19];
    const float* g1b = (const float*)d_in[20];
    const float* be1b= (const float*)d_in[21];
    const float* w3a = (const float*)d_in[22];
    const float* b3a = (const float*)d_in[23];
    const float* g3a = (const float*)d_in[24];
    const float* be3a= (const float*)d_in[25];
    const float* w3b = (const float*)d_in[26];
    const float* b3b = (const float*)d_in[27];
    float* out = (float*)d_out;

    const int SMEMSZ = 65536;
    const int SMUP = 23392 * 4;
    cudaFuncSetAttribute(k_gemmA<1,1>, cudaFuncAttributeMaxDynamicSharedMemorySize, SMEMSZ);
    cudaFuncSetAttribute(k_gemmA<0,0>, cudaFuncAttributeMaxDynamicSharedMemorySize, SMEMSZ);
    cudaFuncSetAttribute(k_gemmA<2,0>, cudaFuncAttributeMaxDynamicSharedMemorySize, SMEMSZ);
    cudaFuncSetAttribute(k_up2, cudaFuncAttributeMaxDynamicSharedMemorySize, SMUP);

    float *p_lowT, *p_embw, *p_x1T, *p_x2T, *p_head, *p_fin, *p_y1T, *p_y2T, *p_zT, *p_w2p;
    float *p_w0ad, *p_w0bd, *p_w2pd, *p_w1ad, *p_w1bd, *p_w3ad;
    cudaGetSymbolAddress((void**)&p_lowT, g_lowT);
    cudaGetSymbolAddress((void**)&p_embw, g_embw);
    cudaGetSymbolAddress((void**)&p_x1T,  g_x1T);
    cudaGetSymbolAddress((void**)&p_x2T,  g_x2T);
    cudaGetSymbolAddress((void**)&p_head, g_head);
    cudaGetSymbolAddress((void**)&p_fin,  g_fineinT);
    cudaGetSymbolAddress((void**)&p_y1T,  g_y1T);
    cudaGetSymbolAddress((void**)&p_y2T,  g_y2T);
    cudaGetSymbolAddress((void**)&p_zT,   g_zT);
    cudaGetSymbolAddress((void**)&p_w2p,  g_w2p);
    cudaGetSymbolAddress((void**)&p_w0ad, g_w0ad);
    cudaGetSymbolAddress((void**)&p_w0bd, g_w0bd);
    cudaGetSymbolAddress((void**)&p_w2pd, g_w2pd);
    cudaGetSymbolAddress((void**)&p_w1ad, g_w1ad);
    cudaGetSymbolAddress((void**)&p_w1bd, g_w1bd);
    cudaGetSymbolAddress((void**)&p_w3ad, g_w3ad);

    k_prelude<<<132, 256>>>((const unsigned*)dm1, w2);
    // pre-dup B images (exact smem layouts)
    k_dupB<<<4 * 10, 256>>>(w0a, NF4, 160, NF4, p_w0ad, 10);
    k_dupB<<<2 * 32, 256>>>(w0b, NF2, NF4, NF2, p_w0bd, 32);
    k_dupB<<<1 * 16, 256>>>(p_w2p, 128, NF2, 128, p_w2pd, 16);
    k_dupB<<<1 * 21, 256>>>(w1a, NFEAT, FINEIN, NFEAT, p_w1ad, 21);
    k_dupB<<<1 *  8, 256>>>(w1b, NFEAT, NFEAT, NFEAT, p_w1bd, 8);
    k_dupB<<<1 *  8, 256>>>(w3a, 64, NFEAT, 64, p_w3ad, 8);

    k_lowT<<<(160 * NLOW) / 256, 256>>>(emb, pe);
    k_gemmA<2,0><<<dim3(NF4/128, NLOW/256), 256, SMEMSZ>>>(p_lowT, p_w0ad, b0a, b0a, b0a, p_embw, NLOW, NF4, NLOW, NF4, 10);
    k_posw<<<(256 * NF4) / 256, 256>>>(w0a);
    k_up2<<<dim3(NF4 / UP_JT, 16, 2), 256, SMUP>>>(b0a, g0a, be0a);

    // coarse MLP layers 2,3
    k_gemmA<1,1><<<dim3(NF2/128, NTOT/256), 256, SMEMSZ>>>(p_x1T, p_w0bd, b0b, g0b, be0b, p_x2T, NTOT, NF2, NTOT, NTOT, 32);
    k_gemmA<0,0><<<dim3(1, NTOT/256), 256, SMEMSZ>>>(p_x2T, p_w2pd, b2, b2, b2, p_head, NTOT, 128, NTOT, 128, 16);
    k_hcol<<<NTOT/256, 256>>>(b2);

    k_post<<<NTOT/8, 256>>>(dm1, dm2);

    int hb = (NTOT + 255) / 256;
    k_hist<<<hb, 256>>>(0);
    k_scan2<<<1, 256>>>(0);
    k_hist<<<hb, 256>>>(1);
    k_scan2<<<1, 256>>>(1);
    k_hist<<<hb, 256>>>(2);
    k_scan2<<<1, 256>>>(2);
    k_compact<<<hb, 256>>>(out);
    k_eqsel<<<1, 256>>>();

    {
        size_t tot = (size_t)KPF * MT;
        k_gatherfine<<<(unsigned)((tot + 255) / 256), 256>>>(emb, pe, dm2);
    }

    // fine MLP
    int gy = (KSEL + 255) / 256;
    k_gemmA<1,1><<<dim3(1, gy), 256, SMEMSZ>>>(p_fin, p_w1ad, b1a, g1a, be1a, p_y1T, KSEL, NFEAT, MT, MT, 21);
    k_gemmA<1,1><<<dim3(1, gy), 256, SMEMSZ>>>(p_y1T, p_w1bd, b1b, g1b, be1b, p_y2T, KSEL, NFEAT, MT, MT, 8);
    k_gemmA<1,1><<<dim3(1, gy), 256, SMEMSZ>>>(p_y2T, p_w3ad, b3a, g3a, be3a, p_zT, KSEL, 64, MT, MT, 8);

    k_zdot<<<(KSEL * 32 + 255) / 256, 256>>>(w3b, b3b, out);
}

// round 17
// speedup vs baseline: 1.5937x; 1.5937x over previous
#include <cuda_runtime.h>
#include <math.h>
#include <stdint.h>

#define NTOT   131072
#define CEMB   32
#define CPE    128
#define INDIM  202
#define NF4    512
#define NF2    256
#define NHEAD  129
#define NFEAT  128
#define FINEIN 330
#define KPF    336
#define KSEL   26214
#define MT     26368
#define NLOW   8192
#define INVF        0.9999950000374997f
#define TWO_PI_F    6.2831854820251465f
#define HALF_PI_F   1.5707963705062866f

// ---------------- scratch ----------------
__device__ float g_lowT   [ (size_t)160 * NLOW ];
__device__ float g_embw   [ (size_t)NLOW * NF4 ];
__device__ float g_posy   [ 256 * NF4 ];
__device__ float g_posx   [ 256 * NF4 ];
__device__ float g_x1T    [ (size_t)NF4 * NTOT ];
__device__ float g_x2T    [ (size_t)NF2 * NTOT ];
__device__ float g_head   [ (size_t)NTOT * NFEAT ];
__device__ float g_hcol   [ NTOT ];
__device__ float g_segc   [ NTOT ];
__device__ float g_var    [ NTOT ];
__device__ float g_fineinT[ (size_t)KPF * MT ];
__device__ float g_y1T    [ (size_t)NFEAT * MT ];
__device__ float g_y2T    [ (size_t)NFEAT * MT ];
__device__ float g_zT     [ (size_t)64 * MT ];
__device__ float g_w2p    [ 256 * 128 ];
__device__ float g_w2c    [ 256 ];
__device__ int   g_sel    [ KSEL ];
__device__ int   g_eq     [ 8192 ];
__device__ unsigned g_hist[3][2048];
__device__ unsigned g_cnt_gt, g_cnt_eq;
__device__ unsigned g_thresh_bits;
__device__ int      g_need_eq;
__device__ unsigned g_bin[3];
__device__ unsigned g_need_s;
__device__ int      g_maskmode;
__device__ float g_tab[256][20];
__device__ float g_coord[256];

// ---------------- cp.async helpers ----------------
__device__ __forceinline__ void cpasync16(uint32_t saddr, const void* gaddr) {
    asm volatile("cp.async.cg.shared.global [%0], [%1], 16;" :: "r"(saddr), "l"(gaddr));
}
#define CP_COMMIT() asm volatile("cp.async.commit_group;" ::: "memory")
#define CP_WAIT0()  asm volatile("cp.async.wait_group 0;" ::: "memory")

// ---------------- mask dtype ----------------
__device__ __forceinline__ float maskval(const void* p, size_t idx, int mode) {
    switch (mode) {
        case 0: return ((const unsigned char*)p)[idx] ? 1.f : 0.f;
        case 1: return ((const int*)p)[idx] ? 1.f : 0.f;
        case 2: return ((const float*)p)[idx];
        case 3: return ((const long long*)p)[idx] ? 1.f : 0.f;
        default: return (float)((const double*)p)[idx];
    }
}

// ---------------- merged prelude ----------------
__global__ void k_prelude(const unsigned* __restrict__ dm, const float* __restrict__ w2) {
    int bid = blockIdx.x, t = threadIdx.x;
    if (bid == 0) {
        __shared__ int sf[4];
        if (t < 4) sf[t] = 0;
        __syncthreads();
        bool f32 = false, f64 = false, gt1 = false, oddnz = false;
        for (int i = t; i < 2048; i += 256) {
            unsigned v = dm[i];
            if (v == 0x3F800000u) f32 = true;
            else if (v == 0x3FF00000u) { if (i & 1) f64 = true; else gt1 = true; }
            else if (v > 1u) gt1 = true;
            if ((i & 1) && v) oddnz = true;
        }
        if (f32)  atomicOr(&sf[0], 1);
        if (f64)  atomicOr(&sf[1], 1);
        if (gt1)  atomicOr(&sf[2], 1);
        if (oddnz) atomicOr(&sf[3], 1);
        __syncthreads();
        if (t == 0) {
            int mode;
            if (sf[1]) mode = 4;
            else if (sf[0]) mode = 2;
            else if (sf[2]) mode = 0;
            else if (!sf[3]) mode = 3;
            else mode = 1;
            g_maskmode = mode;
        }
    } else if (bid == 1) {
        unsigned* h = &g_hist[0][0];
        for (int i = t; i < 3 * 2048; i += 256) h[i] = 0u;
        if (t == 0) { g_cnt_gt = 0u; g_cnt_eq = 0u; }
    } else if (bid == 2) {
        const float step = 2.0f / 255.0f;
        float c = __fadd_rn(-1.0f, __fmul_rn((float)t, step));
        g_coord[t] = c;
        float sc = __fmul_rn(TWO_PI_F, c);
        const float f109 = 10.0f / 9.0f;
        for (int j = 0; j < 10; j++) {
            float xj = __fmul_rn((float)j, f109);
            float fr = (float)exp2((double)xj);
            float ph = __fmul_rn(sc, fr);
            g_tab[t][j]      = (float)sin((double)ph);
            float ph2 = __fadd_rn(ph, HALF_PI_F);
            g_tab[t][10 + j] = (float)sin((double)ph2);
        }
    } else {
        int i = (bid - 3) * 256 + t;
        if (i < 256 * 129) {
            int k = i / 129, j = i - k * 129;
            float v = w2[i];
            if (j < 128) g_w2p[k * 128 + j] = v;
            else g_w2c[k] = v;
        }
    }
}

// ---------------- low-res feat (transposed) ----------------
__global__ void k_lowT(const float* __restrict__ emb, const float* __restrict__ pe) {
    int idx = blockIdx.x * 256 + threadIdx.x;
    if (idx >= 160 * NLOW) return;
    int c = idx >> 13;
    int m = idx & (NLOW - 1);
    int b = m >> 12, p = m & 4095;
    float v = (c < CEMB) ? emb[((size_t)(b * CEMB + c)) * 4096 + p]
                         : pe [((size_t)(b * CPE + (c - CEMB))) * 4096 + p];
    g_lowT[idx] = v;
}

// ---------------- pos weight tables ----------------
__global__ void k_posw(const float* __restrict__ w0a) {
    int idx = blockIdx.x * 256 + threadIdx.x;
    if (idx >= 256 * NF4) return;
    int v = idx >> 9, j = idx & 511;
    float ay = 0.f, ax = 0.f;
    #pragma unroll
    for (int t = 0; t < 10; t++) ay = fmaf(g_tab[v][t],      w0a[(160 + t) * NF4 + j], ay);
    #pragma unroll
    for (int t = 0; t < 10; t++) ay = fmaf(g_tab[v][10 + t], w0a[(180 + t) * NF4 + j], ay);
    ay = fmaf(g_coord[v], w0a[200 * NF4 + j], ay);
    #pragma unroll
    for (int t = 0; t < 10; t++) ax = fmaf(g_tab[v][t],      w0a[(170 + t) * NF4 + j], ax);
    #pragma unroll
    for (int t = 0; t < 10; t++) ax = fmaf(g_tab[v][10 + t], w0a[(190 + t) * NF4 + j], ax);
    ax = fmaf(g_coord[v], w0a[201 * NF4 + j], ax);
    g_posy[idx] = ay;
    g_posx[idx] = ax;
}

// ---------------- FFMA2 SGEMM (cp.async A-staging, register-path B) ----------
#define FFMA2(d,a,b) asm("fma.rn.f32x2 %0, %1, %2, %0;" : "+l"(d) : "l"(a), "l"(b))

template<int EPI, int TRANSC>
__global__ void __launch_bounds__(256, 1) k_gemm2(
    const float* __restrict__ At, const float* __restrict__ B,
    const float* __restrict__ bias, const float* __restrict__ g,
    const float* __restrict__ be, float* __restrict__ C,
    int M, int Kpad, int Klog, int N, int ldA, int ldB, int ldC)
{
    extern __shared__ float sm[];
    float* As = sm;
    float* Bd = sm + 8192;
    const int t = threadIdx.x;
    const int bm = blockIdx.y * 256, bn = blockIdx.x * 128;
    const int tr = t >> 4, tc = t & 15;

    const float4* At4 = (const float4*)At;
    const float4* B4  = (const float4*)B;
    const int lda4 = ldA >> 2, ldb4 = ldB >> 2;
    const uint32_t sAs = (uint32_t)__cvta_generic_to_shared(As);

    float4 rb[2];
    unsigned long long acc[8][8];
    #pragma unroll
    for (int i = 0; i < 8; i++)
        #pragma unroll
        for (int j = 0; j < 8; j++) acc[i][j] = 0ull;

    auto LOADA = [&](int k0, int buf) {
        uint32_t base = sAs + (unsigned)buf * 4096u * 4u;
        #pragma unroll
        for (int i = 0; i < 4; i++) {
            int f = t + 256 * i;
            int kk = f >> 6, m4 = f & 63;
            cpasync16(base + (unsigned)(kk * 256 + m4 * 4) * 4u,
                      &At4[(size_t)(k0 + kk) * lda4 + (bm >> 2) + m4]);
        }
    };
    auto LOADB = [&](int k0) {
        #pragma unroll
        for (int i = 0; i < 2; i++) {
            int f = t + 256 * i;
            int kk = f >> 5, c4 = f & 31;
            int gk = k0 + kk, gn = bn + c4 * 4;
            if (gk < Klog && gn < N) rb[i] = B4[(size_t)gk * ldb4 + (gn >> 2)];
            else rb[i] = make_float4(0.f, 0.f, 0.f, 0.f);
        }
    };
    auto STOREB = [&](int buf) {
        float* Bdb = Bd + buf * 4096;
        #pragma unroll
        for (int i = 0; i < 2; i++) {
            int f = t + 256 * i;
            int kk = f >> 5, c4 = f & 31;
            int tcb = c4 >> 1, qb = (c4 & 1) * 2;
            *(float4*)&Bdb[((kk * 4 + qb) * 16 + tcb) * 4] =
                make_float4(rb[i].x, rb[i].x, rb[i].y, rb[i].y);
            *(float4*)&Bdb[((kk * 4 + qb + 1) * 16 + tcb) * 4] =
                make_float4(rb[i].z, rb[i].z, rb[i].w, rb[i].w);
        }
    };
    auto COMPUTE = [&](int buf) {
        const float* Asb = As + buf * 4096;
        const float* Bdb = Bd + buf * 4096;
        #pragma unroll
        for (int kk = 0; kk < 16; kk++) {
            unsigned long long a2[8], b2[8];
            #pragma unroll
            for (int r = 0; r < 4; r++) {
                ulonglong2 v = *(const ulonglong2*)&Asb[kk * 256 + tr * 16 + r * 4];
                a2[2 * r] = v.x; a2[2 * r + 1] = v.y;
            }
            #pragma unroll
            for (int q = 0; q < 4; q++) {
                ulonglong2 v = *(const ulonglong2*)&Bdb[(kk * 4 + q) * 64 + tc * 4];
                b2[2 * q] = v.x; b2[2 * q + 1] = v.y;
            }
            #pragma unroll
            for (int ip = 0; ip < 8; ip++)
                #pragma unroll
                for (int j = 0; j < 8; j++)
                    FFMA2(acc[ip][j], a2[ip], b2[j]);
        }
    };

    LOADA(0, 0); LOADB(0); STOREB(0);
    CP_COMMIT(); CP_WAIT0();
    __syncthreads();
    int nk = Kpad >> 4;
    int buf = 0;
    for (int it = 1; it < nk; it++) {
        LOADA(it * 16, buf ^ 1);   // async copy overlaps COMPUTE below
        CP_COMMIT();
        LOADB(it * 16);
        COMPUTE(buf);
        STOREB(buf ^ 1);
        CP_WAIT0();
        __syncthreads();
        buf ^= 1;
    }
    COMPUTE(buf);

    if (TRANSC) {
        #pragma unroll
        for (int j = 0; j < 8; j++) {
            int gn = bn + tc * 8 + j;
            if (gn >= N) continue;
            float bsv = (EPI != 2) ? bias[gn] : 0.f;
            float sv = 0.f, bev = 0.f;
            if (EPI == 1) { sv = __fmul_rn(g[gn], INVF); bev = be[gn]; }
            float v[16];
            #pragma unroll
            for (int ip = 0; ip < 8; ip++) {
                v[2 * ip]     = __uint_as_float((unsigned)(acc[ip][j] & 0xFFFFFFFFull));
                v[2 * ip + 1] = __uint_as_float((unsigned)(acc[ip][j] >> 32));
            }
            #pragma unroll
            for (int r = 0; r < 16; r++) {
                float x = v[r];
                if (EPI != 2) x = __fadd_rn(x, bsv);
                if (EPI == 1) { x = __fadd_rn(__fmul_rn(x, sv), bev); x = fmaxf(x, 0.f); }
                v[r] = x;
            }
            int gmb = bm + tr * 16;
            if (gmb + 16 <= M) {
                #pragma unroll
                for (int r4 = 0; r4 < 4; r4++)
                    *(float4*)&C[(size_t)gn * ldC + gmb + r4 * 4] =
                        make_float4(v[r4 * 4], v[r4 * 4 + 1], v[r4 * 4 + 2], v[r4 * 4 + 3]);
            } else {
                for (int r = 0; r < 16; r++)
                    if (gmb + r < M) C[(size_t)gn * ldC + gmb + r] = v[r];
            }
        }
    } else {
        #pragma unroll
        for (int ip = 0; ip < 8; ip++) {
            #pragma unroll
            for (int h = 0; h < 2; h++) {
                int gm = bm + tr * 16 + 2 * ip + h;
                if (gm >= M) continue;
                float v[8];
                #pragma unroll
                for (int j = 0; j < 8; j++) {
                    unsigned long long a = acc[ip][j];
                    float x = h ? __uint_as_float((unsigned)(a >> 32))
                                : __uint_as_float((unsigned)(a & 0xFFFFFFFFull));
                    int gn = bn + tc * 8 + j;
                    if (EPI != 2) x = __fadd_rn(x, bias[gn]);
                    if (EPI == 1) {
                        x = __fadd_rn(__fmul_rn(x, __fmul_rn(g[gn], INVF)), be[gn]);
                        x = fmaxf(x, 0.f);
                    }
                    v[j] = x;
                }
                int gn0 = bn + tc * 8;
                if (gn0 + 8 <= N) {
                    *(float4*)&C[(size_t)gm * ldC + gn0]     = make_float4(v[0], v[1], v[2], v[3]);
                    *(float4*)&C[(size_t)gm * ldC + gn0 + 4] = make_float4(v[4], v[5], v[6], v[7]);
                } else {
                    for (int j = 0; j < 8; j++)
                        if (gn0 + j < N) C[(size_t)gm * ldC + gn0 + j] = v[j];
                }
            }
        }
    }
}

// ---------------- tiled upsample + pos + bn -> x1T (bit-exact) ----------------
#define UP_JT 32
__global__ void __launch_bounds__(256) k_up2(
    const float* __restrict__ b0a, const float* __restrict__ g0a,
    const float* __restrict__ be0a)
{
    extern __shared__ float su[];
    float* E  = su;
    float* PX = su + 12288;
    float* T  = su + 20480;
    float* PY = su + 22784;
    float* PR = su + 23296;
    const int t = threadIdx.x;
    const int j0 = blockIdx.x * UP_JT, y0 = blockIdx.y * 16, b = blockIdx.z;

    float cyf0 = ((float)y0 + 0.5f) * 0.25f - 0.5f;
    int base = max(0, (int)floorf(cyf0));

    for (int i = t; i < 6 * 64 * (UP_JT / 4); i += 256) {
        int r = i / (64 * (UP_JT / 4));
        int rem = i - r * 64 * (UP_JT / 4);
        int ix = rem / (UP_JT / 4), jq = rem % (UP_JT / 4);
        int gy = min(base + r, 63);
        *(float4*)&E[(r * 64 + ix) * UP_JT + jq * 4] =
            *(const float4*)&g_embw[((size_t)(b * 4096 + gy * 64 + ix)) * NF4 + j0 + jq * 4];
    }
    for (int i = t; i < 256 * (UP_JT / 4); i += 256) {
        int x = i / (UP_JT / 4), jq = i % (UP_JT / 4);
        *(float4*)&PX[x * UP_JT + jq * 4] = *(const float4*)&g_posx[x * NF4 + j0 + jq * 4];
    }
    if (t < 16 * (UP_JT / 4)) {
        int y = t / (UP_JT / 4), jq = t % (UP_JT / 4);
        *(float4*)&PY[y * UP_JT + jq * 4] = *(const float4*)&g_posy[(y0 + y) * NF4 + j0 + jq * 4];
    }
    if (t >= 128 && t < 128 + 3 * (UP_JT / 4)) {
        int a = (t - 128) / (UP_JT / 4), jq = (t - 128) % (UP_JT / 4);
        const float* src = (a == 0) ? b0a : (a == 1) ? g0a : be0a;
        *(float4*)&PR[a * UP_JT + jq * 4] = *(const float4*)&src[j0 + jq * 4];
    }
    __syncthreads();

    for (int yy = 0; yy < 16; yy++) {
        int y = y0 + yy;
        float cyf = ((float)y + 0.5f) * 0.25f - 0.5f;
        float fy0f = floorf(cyf);
        float fy = cyf - fy0f;
        int yi = (int)fy0f;
        int iy0 = min(max(yi, 0), 63), iy1 = min(max(yi + 1, 0), 63);
        bool yeq = (iy0 == iy1);
        float wy0 = 1.f - fy;
        int r0 = iy0 - base, r1 = iy1 - base;

        for (int i = t; i < 64 * (UP_JT / 4); i += 256) {
            int ix = i / (UP_JT / 4), jq = i % (UP_JT / 4);
            float4 v0 = *(const float4*)&E[(r0 * 64 + ix) * UP_JT + jq * 4];
            float4 vv;
            if (yeq) vv = v0;
            else {
                float4 v1 = *(const float4*)&E[(r1 * 64 + ix) * UP_JT + jq * 4];
                vv.x = __fadd_rn(__fmul_rn(v0.x, wy0), __fmul_rn(v1.x, fy));
                vv.y = __fadd_rn(__fmul_rn(v0.y, wy0), __fmul_rn(v1.y, fy));
                vv.z = __fadd_rn(__fmul_rn(v0.z, wy0), __fmul_rn(v1.z, fy));
                vv.w = __fadd_rn(__fmul_rn(v0.w, wy0), __fmul_rn(v1.w, fy));
            }
            *(float4*)&T[ix * 36 + jq * 4] = vv;
        }
        __syncthreads();

        int x = t;
        int k = x >> 2, xi = x & 3;
        int cL, cR; float fx; bool cp;
        if (xi < 2) { cL = max(k - 1, 0); cR = k; fx = (xi == 0) ? 0.625f : 0.875f; cp = (k == 0); }
        else        { cL = k; cR = min(k + 1, 63); fx = (xi == 2) ? 0.125f : 0.375f; cp = (k == 63); }
        float wx = 1.f - fx;
        size_t n = (size_t)b * 65536 + (size_t)y * 256 + x;

        #pragma unroll
        for (int jq = 0; jq < UP_JT / 4; jq++) {
            float4 TL = *(const float4*)&T[cL * 36 + jq * 4];
            float4 v;
            if (cp) v = TL;
            else {
                float4 TR = *(const float4*)&T[cR * 36 + jq * 4];
                v.x = __fadd_rn(__fmul_rn(TL.x, wx), __fmul_rn(TR.x, fx));
                v.y = __fadd_rn(__fmul_rn(TL.y, wx), __fmul_rn(TR.y, fx));
                v.z = __fadd_rn(__fmul_rn(TL.z, wx), __fmul_rn(TR.z, fx));
                v.w = __fadd_rn(__fmul_rn(TL.w, wx), __fmul_rn(TR.w, fx));
            }
            float4 py  = *(const float4*)&PY[yy * UP_JT + jq * 4];
            float4 px  = *(const float4*)&PX[x * UP_JT + jq * 4];
            float4 bsv = *(const float4*)&PR[0 * UP_JT + jq * 4];
            float4 gv  = *(const float4*)&PR[1 * UP_JT + jq * 4];
            float4 bev = *(const float4*)&PR[2 * UP_JT + jq * 4];
            v.x = __fadd_rn(__fadd_rn(__fadd_rn(v.x, py.x), px.x), bsv.x);
            v.y = __fadd_rn(__fadd_rn(__fadd_rn(v.y, py.y), px.y), bsv.y);
            v.z = __fadd_rn(__fadd_rn(__fadd_rn(v.z, py.z), px.z), bsv.z);
            v.w = __fadd_rn(__fadd_rn(__fadd_rn(v.w, py.w), px.w), bsv.w);
            v.x = fmaxf(__fadd_rn(__fmul_rn(v.x, __fmul_rn(gv.x, INVF)), bev.x), 0.f);
            v.y = fmaxf(__fadd_rn(__fmul_rn(v.y, __fmul_rn(gv.y, INVF)), bev.y), 0.f);
            v.z = fmaxf(__fadd_rn(__fmul_rn(v.z, __fmul_rn(gv.z, INVF)), bev.z), 0.f);
            v.w = fmaxf(__fadd_rn(__fmul_rn(v.w, __fmul_rn(gv.w, INVF)), bev.w), 0.f);
            int j = j0 + jq * 4;
            g_x1T[(size_t)(j + 0) * NTOT + n] = v.x;
            g_x1T[(size_t)(j + 1) * NTOT + n] = v.y;
            g_x1T[(size_t)(j + 2) * NTOT + n] = v.z;
            g_x1T[(size_t)(j + 3) * NTOT + n] = v.w;
        }
        __syncthreads();
    }
}

// ---------------- head col 128 ----------------
__global__ void k_hcol(const float* __restrict__ b2) {
    int n = blockIdx.x * 256 + threadIdx.x;
    float acc = 0.f;
    #pragma unroll 8
    for (int k = 0; k < 256; k++)
        acc = fmaf(g_x2T[(size_t)k * NTOT + n], g_w2c[k], acc);
    g_hcol[n] = __fadd_rn(acc, b2[128]);
}

// ---------------- head post: segc / var ----------------
__global__ void k_post(const void* __restrict__ dm1, const void* __restrict__ dm2) {
    int w = (int)((blockIdx.x * (size_t)blockDim.x + threadIdx.x) >> 5);
    int lane = threadIdx.x & 31;
    if (w >= NTOT) return;
    int mode = g_maskmode;
    float acc = 0.f;
    for (int c = lane; c < NHEAD; c += 32) {
        float h = (c < 128) ? g_head[(size_t)w * 128 + c] : g_hcol[w];
        size_t mi = (size_t)w * NHEAD + c;
        float m1 = maskval(dm1, mi, mode);
        float m2 = maskval(dm2, mi, mode);
        float o2 = __fmul_rn(__fmul_rn(h, m2), 2.0f);
        if (c == 0) g_segc[w] = o2;
        float o1 = __fmul_rn(__fmul_rn(h, m1), 2.0f);
        float d  = __fsub_rn(o1, o2);
        acc = __fadd_rn(acc, __fmul_rn(0.5f, __fmul_rn(d, d)));
    }
    #pragma unroll
    for (int o = 16; o; o >>= 1) acc = __fadd_rn(acc, __shfl_xor_sync(~0u, acc, o));
    if (!lane) g_var[w] = __fdiv_rn(acc, 129.0f);
}

// ---------------- top-k ----------------
__global__ void k_hist(int phase) {
    int i = blockIdx.x * blockDim.x + threadIdx.x;
    if (i >= NTOT) return;
    unsigned key = __float_as_uint(g_var[i]);
    if (phase == 0) atomicAdd(&g_hist[0][key >> 21], 1u);
    else if (phase == 1) {
        if ((key >> 21) == g_bin[0]) atomicAdd(&g_hist[1][(key >> 10) & 0x7FFu], 1u);
    } else {
        if ((key >> 10) == ((g_bin[0] << 11) | g_bin[1]))
            atomicAdd(&g_hist[2][key & 0x3FFu], 1u);
    }
}

__global__ void k_scan2(int phase) {
    __shared__ unsigned csum[256];
    __shared__ unsigned suf[256];
    int t = threadIdx.x;
    unsigned need = (phase == 0) ? (unsigned)KSEL : g_need_s;
    const unsigned* H = g_hist[phase];
    unsigned h[8]; unsigned s = 0;
    #pragma unroll
    for (int i = 0; i < 8; i++) { h[i] = H[t * 8 + i]; s += h[i]; }
    csum[t] = s;
    __syncthreads();
    if (t == 0) {
        unsigned a = 0;
        for (int u = 255; u >= 0; u--) { suf[u] = a; a += csum[u]; }
    }
    __syncthreads();
    unsigned se = suf[t];
    if (se < need && se + csum[t] >= need) {
        unsigned acc = se;
        int b = -1;
        int lo = (t == 0) ? 1 : 0;
        for (int i = 7; i >= lo; i--) {
            unsigned hh = h[i];
            if (acc + hh >= need) { b = t * 8 + i; break; }
            acc += hh;
        }
        if (b < 0) b = 0;
        g_bin[phase] = (unsigned)b;
        g_need_s = need - acc;
        if (phase == 2) {
            g_thresh_bits = (g_bin[0] << 21) | (g_bin[1] << 10) | (unsigned)b;
            g_need_eq = (int)(need - acc);
        }
    }
}

__global__ void k_compact(float* __restrict__ out) {
    int i = blockIdx.x * blockDim.x + threadIdx.x;
    if (i >= NTOT) return;
    float vv = g_segc[i];
    out[i] = vv;
    out[NTOT + i] = vv;
    unsigned key = __float_as_uint(g_var[i]);
    unsigned T = g_thresh_bits;
    if (key > T) {
        unsigned s = atomicAdd(&g_cnt_gt, 1u);
        g_sel[s] = i;
    } else if (key == T) {
        unsigned e = atomicAdd(&g_cnt_eq, 1u);
        if (e < 8192u) g_eq[e] = i;
    }
}

__global__ void k_eqsel() {
    int c = (int)g_cnt_eq; if (c > 8192) c = 8192;
    int need = g_need_eq;
    int G = KSEL - need;
    for (int i = threadIdx.x; i < c; i += blockDim.x) {
        int v = g_eq[i];
        int rank = 0;
        for (int j = 0; j < c; j++) rank += (g_eq[j] < v) ? 1 : 0;
        if (rank < need) g_sel[G + rank] = v;
    }
}

// ---------------- lazy fine-input build ----------------
__global__ void k_gatherfine(const float* __restrict__ emb, const float* __restrict__ pe,
                             const void* __restrict__ dm2) {
    size_t idx = (size_t)blockIdx.x * 256 + threadIdx.x;
    if (idx >= (size_t)KPF * MT) return;
    int c = (int)(idx / MT);
    int j = (int)(idx - (size_t)c * MT);
    float v = 0.f;
    if (j < KSEL && c < FINEIN) {
        int s = g_sel[j];
        int b = s >> 16, y = (s >> 8) & 255, x = s & 255;
        if (c < CEMB + CPE) {
            const float* plane = (c < CEMB)
                ? emb + ((size_t)(b * CEMB + c)) * 4096
                : pe  + ((size_t)(b * CPE + (c - CEMB))) * 4096;
            float cyf = ((float)y + 0.5f) * 0.25f - 0.5f;
            float cxf = ((float)x + 0.5f) * 0.25f - 0.5f;
            float fy0 = floorf(cyf), fx0 = floorf(cxf);
            float fy = cyf - fy0, fx = cxf - fx0;
            int y0 = (int)fy0, x0 = (int)fx0;
            int iy0 = min(max(y0, 0), 63), iy1 = min(max(y0 + 1, 0), 63);
            int ix0 = min(max(x0, 0), 63), ix1 = min(max(x0 + 1, 0), 63);
            float v00 = plane[iy0 * 64 + ix0], v01 = plane[iy0 * 64 + ix1];
            float v10 = plane[iy1 * 64 + ix0], v11 = plane[iy1 * 64 + ix1];
            float wy0 = 1.f - fy, wx0 = 1.f - fx;
            float t0, t1;
            if (iy0 == iy1) { t0 = v00; t1 = v01; }
            else {
                t0 = __fadd_rn(__fmul_rn(v00, wy0), __fmul_rn(v10, fy));
                t1 = __fadd_rn(__fmul_rn(v01, wy0), __fmul_rn(v11, fy));
            }
            v = (ix0 == ix1) ? t0
                : __fadd_rn(__fmul_rn(t0, wx0), __fmul_rn(t1, fx));
        } else if (c < INDIM) {
            int p = c - (CEMB + CPE);
            if      (p < 10) v = g_tab[y][p];
            else if (p < 20) v = g_tab[x][p - 10];
            else if (p < 30) v = g_tab[y][p - 10];
            else if (p < 40) v = g_tab[x][p - 20];
            else v = (p == 40) ? g_coord[y] : g_coord[x];
        } else {
            int col = c - 201;   // 1..128
            float h = (col < 128) ? g_head[(size_t)s * 128 + col] : g_hcol[s];
            float m2 = maskval(dm2, (size_t)s * NHEAD + col, g_maskmode);
            v = __fmul_rn(__fmul_rn(h, m2), 2.0f);
        }
    }
    g_fineinT[idx] = v;
}

// ---------------- final fine dot + scatter ----------------
__global__ void k_zdot(const float* __restrict__ w3b, const float* __restrict__ b3b,
                       float* __restrict__ out) {
    int j = (int)((blockIdx.x * (size_t)blockDim.x + threadIdx.x) >> 5);
    int lane = threadIdx.x & 31;
    if (j >= KSEL) return;
    float v0  = g_zT[(size_t)lane * MT + j];
    float v32 = g_zT[(size_t)(32 + lane) * MT + j];
    float acc = __fadd_rn(__fmul_rn(v0, w3b[lane]), __fmul_rn(v32, w3b[32 + lane]));
    #pragma unroll
    for (int o = 16; o; o >>= 1) acc = __fadd_rn(acc, __shfl_xor_sync(~0u, acc, o));
    if (!lane) out[NTOT + g_sel[j]] = __fadd_rn(acc, b3b[0]);
}

// ---------------- launch ----------------
extern "C" void kernel_launch(void* const* d_in, const int* in_sizes, int n_in,
                              void* d_out, int out_size) {
    const float* emb = (const float*)d_in[0];
    const float* pe  = (const float*)d_in[1];
    const void*  dm1 = d_in[2];
    const void*  dm2 = d_in[3];
    const float* w0a = (const float*)d_in[4];
    const float* b0a = (const float*)d_in[5];
    const float* g0a = (const float*)d_in[6];
    const float* be0a= (const float*)d_in[7];
    const float* w0b = (const float*)d_in[8];
    const float* b0b = (const float*)d_in[9];
    const float* g0b = (const float*)d_in[10];
    const float* be0b= (const float*)d_in[11];
    const float* w2  = (const float*)d_in[12];
    const float* b2  = (const float*)d_in[13];
    const float* w1a = (const float*)d_in[14];
    const float* b1a = (const float*)d_in[15];
    const float* g1a = (const float*)d_in[16];
    const float* be1a= (const float*)d_in[17];
    const float* w1b = (const float*)d_in[18];
    const float* b1b = (const float*)d_in[19];
    const float* g1b = (const float*)d_in[20];
    const float* be1b= (const float*)d_in[21];
    const float* w3a = (const float*)d_in[22];
    const float* b3a = (const float*)d_in[23];
    const float* g3a = (const float*)d_in[24];
    const float* be3a= (const float*)d_in[25];
    const float* w3b = (const float*)d_in[26];
    const float* b3b = (const float*)d_in[27];
    float* out = (float*)d_out;

    const int SMEMSZ = 65536;
    const int SMUP = 23392 * 4;
    cudaFuncSetAttribute(k_gemm2<1,1>, cudaFuncAttributeMaxDynamicSharedMemorySize, SMEMSZ);
    cudaFuncSetAttribute(k_gemm2<0,0>, cudaFuncAttributeMaxDynamicSharedMemorySize, SMEMSZ);
    cudaFuncSetAttribute(k_gemm2<2,0>, cudaFuncAttributeMaxDynamicSharedMemorySize, SMEMSZ);
    cudaFuncSetAttribute(k_up2, cudaFuncAttributeMaxDynamicSharedMemorySize, SMUP);

    float *p_lowT, *p_embw, *p_x1T, *p_x2T, *p_head, *p_fin, *p_y1T, *p_y2T, *p_zT, *p_w2p;
    cudaGetSymbolAddress((void**)&p_lowT, g_lowT);
    cudaGetSymbolAddress((void**)&p_embw, g_embw);
    cudaGetSymbolAddress((void**)&p_x1T,  g_x1T);
    cudaGetSymbolAddress((void**)&p_x2T,  g_x2T);
    cudaGetSymbolAddress((void**)&p_head, g_head);
    cudaGetSymbolAddress((void**)&p_fin,  g_fineinT);
    cudaGetSymbolAddress((void**)&p_y1T,  g_y1T);
    cudaGetSymbolAddress((void**)&p_y2T,  g_y2T);
    cudaGetSymbolAddress((void**)&p_zT,   g_zT);
    cudaGetSymbolAddress((void**)&p_w2p,  g_w2p);

    k_prelude<<<132, 256>>>((const unsigned*)dm1, w2);
    k_lowT<<<(160 * NLOW) / 256, 256>>>(emb, pe);
    k_gemm2<2,0><<<dim3(NF4/128, NLOW/256), 256, SMEMSZ>>>(p_lowT, w0a, b0a, b0a, b0a, p_embw, NLOW, 160, 160, NF4, NLOW, NF4, NF4);
    k_posw<<<(256 * NF4) / 256, 256>>>(w0a);
    k_up2<<<dim3(NF4 / UP_JT, 16, 2), 256, SMUP>>>(b0a, g0a, be0a);

    // coarse MLP layers 2,3
    k_gemm2<1,1><<<dim3(NF2/128, NTOT/256), 256, SMEMSZ>>>(p_x1T, w0b, b0b, g0b, be0b, p_x2T, NTOT, NF4, NF4, NF2, NTOT, NF2, NTOT);
    k_gemm2<0,0><<<dim3(1, NTOT/256), 256, SMEMSZ>>>(p_x2T, p_w2p, b2, b2, b2, p_head, NTOT, NF2, NF2, 128, NTOT, 128, 128);
    k_hcol<<<NTOT/256, 256>>>(b2);

    k_post<<<NTOT/8, 256>>>(dm1, dm2);

    int hb = (NTOT + 255) / 256;
    k_hist<<<hb, 256>>>(0);
    k_scan2<<<1, 256>>>(0);
    k_hist<<<hb, 256>>>(1);
    k_scan2<<<1, 256>>>(1);
    k_hist<<<hb, 256>>>(2);
    k_scan2<<<1, 256>>>(2);
    k_compact<<<hb, 256>>>(out);
    k_eqsel<<<1, 256>>>();

    {
        size_t tot = (size_t)KPF * MT;
        k_gatherfine<<<(unsigned)((tot + 255) / 256), 256>>>(emb, pe, dm2);
    }

    // fine MLP
    int gy = (KSEL + 255) / 256;
    k_gemm2<1,1><<<dim3(1, gy), 256, SMEMSZ>>>(p_fin, w1a, b1a, g1a, be1a, p_y1T, KSEL, KPF, FINEIN, NFEAT, MT, NFEAT, MT);
    k_gemm2<1,1><<<dim3(1, gy), 256, SMEMSZ>>>(p_y1T, w1b, b1b, g1b, be1b, p_y2T, KSEL, NFEAT, NFEAT, NFEAT, MT, NFEAT, MT);
    k_gemm2<1,1><<<dim3(1, gy), 256, SMEMSZ>>>(p_y2T, w3a, b3a, g3a, be3a, p_zT, KSEL, NFEAT, NFEAT, 64, MT, 64, MT);

    k_zdot<<<(KSEL * 32 + 255) / 256, 256>>>(w3b, b3b, out);
}